// round 16
// baseline (speedup 1.0000x reference)
#include <cuda_runtime.h>
#include <cstdint>

// ---------------------------------------------------------------------------
// DASAttentionGate. B=4, C=O=128, H=W=96, fp32.
// [dw3x3 + pw1x1(TF32x3 MMA) + stats] -> mr -> offconv3x3 (TF32x2 MMA, M=64)
//   -> [fused M=128: gather(norm on the fly) -> TF32x3 MMA -> LN -> gate]
// ---------------------------------------------------------------------------

#define Cc   128
#define Hc   96
#define Wc   96
#define HW   9216
#define PIX  36864
#define PITCH 132
#define BPITCH 68

__device__ float g_h2[PIX * Cc];          // pw out, NHWC (pre-norm)
__device__ float g_stats[1024];
__device__ float g_mr[1024];              // mean[512], rstd[512]
__device__ float g_off[PIX * 18];
__device__ float g_offwB[9 * 32 * 128];   // off weights per tap [n(pad32)][c]
__device__ float g_wB[9 * 16384];         // deform weights per tap: [n*128+c]

// -------------------- TF32 helpers ------------------------------------------
__device__ __forceinline__ uint32_t tf32r(float v) {
    uint32_t r;
    asm("cvt.rna.tf32.f32 %0, %1;" : "=r"(r) : "f"(v));
    return r;
}

#define MMA_TF32(D, A, B0, B1)                                              \
    asm volatile("mma.sync.aligned.m16n8k8.row.col.f32.tf32.tf32.f32 "      \
        "{%0,%1,%2,%3}, {%4,%5,%6,%7}, {%8,%9}, {%0,%1,%2,%3};"             \
        : "+f"((D)[0]), "+f"((D)[1]), "+f"((D)[2]), "+f"((D)[3])            \
        : "r"((A)[0]), "r"((A)[1]), "r"((A)[2]), "r"((A)[3]),               \
          "r"(B0), "r"(B1))

// -------------------- prep: weight images + zero stats ----------------------
__global__ void prep_kernel(const float* __restrict__ dc_w,
                            const float* __restrict__ off_w) {
    int i = blockIdx.x * blockDim.x + threadIdx.x;
    if (i < 9 * 16384) {
        int tap = i >> 14;
        int r   = i & 16383;
        int n   = r >> 7, c = r & 127;
        g_wB[i] = dc_w[(n * 128 + c) * 9 + tap];
    }
    if (i < 9 * 32 * 128) {
        int tap = i >> 12;
        int r   = i & 4095;
        int n   = r >> 7, c = r & 127;
        g_offwB[i] = (n < 18) ? off_w[(n * 128 + c) * 9 + tap] : 0.f;
    }
    if (i < 1024) g_stats[i] = 0.f;
}

// ---------------------------------------------------------------------------
// Fused depthwise 3x3 + pointwise 1x1 (TF32x3 MMA) + InstanceNorm stats.
// Block = 32 px of one row, 256 threads = 8 warps (2M x 4N), warp M16 x N32.
// ---------------------------------------------------------------------------
#define DWPW_SMEM ((32 * PITCH + 128 * PITCH) * 4)

__global__ __launch_bounds__(256, 2) void dwpw_kernel(
        const float* __restrict__ x,
        const float* __restrict__ dw_w,
        const float* __restrict__ dw_b,
        const float* __restrict__ pw_w,
        const float* __restrict__ pw_b) {
    extern __shared__ float smd[];
    float* As = smd;                    // [px][PITCH], 32 rows
    float* Bs = smd + 32 * PITCH;       // [o][PITCH], 128 rows
    float* xt = Bs;                     // halo aliases Bs: [c][r][34] = 13056

    int t  = threadIdx.x;
    int w  = t >> 5, l = t & 31;
    int p0 = blockIdx.x * 32;
    int b  = p0 / HW;
    int s0 = p0 - b * HW;
    int y  = s0 / Wc;
    int x0 = s0 - y * Wc;

    // ---- halo load ----
    for (int f = t; f < 13056; f += 256) {
        int c   = f / 102;
        int rem = f - c * 102;
        int r   = rem / 34;
        int col = rem - r * 34;
        int yy = y + r - 1, xx = x0 + col - 1;
        float v = 0.f;
        if ((unsigned)yy < Hc && (unsigned)xx < Wc)
            v = x[(size_t)(b * 128 + c) * HW + yy * Wc + xx];
        xt[f] = v;
    }
    __syncthreads();

    // ---- depthwise into As[px][c] ----
    {
        int c   = t >> 1;
        int pxb = (t & 1) * 16;
        float wv[9];
#pragma unroll
        for (int j = 0; j < 9; j++) wv[j] = dw_w[c * 9 + j];
        float bias = dw_b[c];
        float accd[16];
#pragma unroll
        for (int p = 0; p < 16; p++) accd[p] = bias;
#pragma unroll
        for (int r = 0; r < 3; r++)
#pragma unroll
            for (int cc = 0; cc < 3; cc++) {
                float wgt = wv[r * 3 + cc];
                const float* src = &xt[c * 102 + r * 34 + pxb + cc];
#pragma unroll
                for (int p = 0; p < 16; p++) accd[p] += wgt * src[p];
            }
#pragma unroll
        for (int p = 0; p < 16; p++) As[(pxb + p) * PITCH + c] = accd[p];
    }
    __syncthreads();

    // ---- load pw weights into Bs[o][c] (overwrites halo) ----
#pragma unroll
    for (int j = 0; j < 16; j++) {
        int f4 = t + j * 256;
        int n = f4 >> 5, c4 = (f4 & 31) << 2;
        *(float4*)&Bs[n * PITCH + c4] = *(const float4*)&pw_w[n * 128 + c4];
    }
    __syncthreads();

    // ---- pw GEMM: [32 x 128] * [128 x 128], TF32x3 ----
    int mbase = (w & 1) * 16;
    int nbase = (w >> 1) * 32;
    int qr = l >> 2;
    int qc = l & 3;

    float d[4][4];
#pragma unroll
    for (int j = 0; j < 4; j++)
#pragma unroll
        for (int q = 0; q < 4; q++) d[j][q] = 0.f;

#pragma unroll 4
    for (int s = 0; s < 16; s++) {
        int k0 = s * 8;
        uint32_t ah[4], al[4];
        {
            int r0 = (mbase + qr) * PITCH + k0 + qc;
            int r1 = r0 + 8 * PITCH;
            float f0 = As[r0], f1 = As[r1], f2 = As[r0 + 4], f3 = As[r1 + 4];
            ah[0] = tf32r(f0); ah[1] = tf32r(f1);
            ah[2] = tf32r(f2); ah[3] = tf32r(f3);
            al[0] = __float_as_uint(f0 - __uint_as_float(ah[0]));
            al[1] = __float_as_uint(f1 - __uint_as_float(ah[1]));
            al[2] = __float_as_uint(f2 - __uint_as_float(ah[2]));
            al[3] = __float_as_uint(f3 - __uint_as_float(ah[3]));
        }
        uint32_t bh[4][2], bl[4][2];
#pragma unroll
        for (int ni = 0; ni < 4; ni++) {
            int nb = (nbase + ni * 8 + qr) * PITCH + k0 + qc;
            float f0 = Bs[nb], f1 = Bs[nb + 4];
            bh[ni][0] = tf32r(f0);
            bh[ni][1] = tf32r(f1);
            bl[ni][0] = __float_as_uint(f0 - __uint_as_float(bh[ni][0]));
            bl[ni][1] = __float_as_uint(f1 - __uint_as_float(bh[ni][1]));
        }
#pragma unroll
        for (int ni = 0; ni < 4; ni++) {
            MMA_TF32(d[ni], ah, bh[ni][0], bh[ni][1]);
            MMA_TF32(d[ni], ah, bl[ni][0], bl[ni][1]);
            MMA_TF32(d[ni], al, bh[ni][0], bh[ni][1]);
        }
    }
    __syncthreads();

    // ---- bias + stage result back into As (sdc[32][PITCH]) ----
    float* sdc = As;
    {
        int row = mbase + qr;
#pragma unroll
        for (int ni = 0; ni < 4; ni++) {
            int col = nbase + ni * 8 + 2 * qc;
            float b0 = pw_b[col], b1 = pw_b[col + 1];
            float2 lo, hi;
            lo.x = d[ni][0] + b0; lo.y = d[ni][1] + b1;
            hi.x = d[ni][2] + b0; hi.y = d[ni][3] + b1;
            *(float2*)&sdc[row * PITCH + col]       = lo;
            *(float2*)&sdc[(row + 8) * PITCH + col] = hi;
        }
    }
    __syncthreads();

    // ---- stats + write g_h2 ----
    {
        int c   = t >> 1;
        int pxb = (t & 1) * 16;
        float sp = 0.f, sq = 0.f;
#pragma unroll
        for (int p = 0; p < 16; p++) {
            float v = sdc[(pxb + p) * PITCH + c];
            sp += v; sq += v * v;
        }
        sp += __shfl_xor_sync(0xffffffffu, sp, 1);
        sq += __shfl_xor_sync(0xffffffffu, sq, 1);
        if ((t & 1) == 0) {
            atomicAdd(&g_stats[b * 128 + c], sp);
            atomicAdd(&g_stats[512 + b * 128 + c], sq);
        }
    }
#pragma unroll
    for (int j = 0; j < 16; j++) {
        int flat = t + j * 256;
        int px = flat >> 7, c = flat & 127;
        g_h2[(size_t)(p0 + px) * 128 + c] = sdc[px * PITCH + c];
    }
}

// -------------------- instance norm finalize ---------------------------------
__global__ void mr_kernel() {
    int i = blockIdx.x * blockDim.x + threadIdx.x;
    if (i >= 512) return;
    float m = g_stats[i] * (1.f / HW);
    float v = g_stats[512 + i] * (1.f / HW) - m * m;
    g_mr[i] = m;
    g_mr[512 + i] = rsqrtf(v + 1e-5f);
}

// ---------------------------------------------------------------------------
// Offset conv 3x3 via TF32x2 MMA: [64px x 1152] * [1152 x 18(pad32)].
// Block: 64 px, 256 threads = 8 warps (4M x 2N), warp M16 x N16.
// smem 50.7KB -> 3 CTAs/SM.
// ---------------------------------------------------------------------------
#define OFF_SMEM ((64 * PITCH + 32 * PITCH) * 4)

__global__ __launch_bounds__(256, 3) void off_mma_kernel(
        const float* __restrict__ off_b) {
    extern __shared__ float smo[];
    float* As = smo;                    // [px][PITCH], 64 rows
    float* Bs = smo + 64 * PITCH;       // [n][PITCH], 32 rows

    int t = threadIdx.x;
    int w = t >> 5, l = t & 31;
    int m0 = blockIdx.x * 64;
    int b  = m0 / HW;
    int s0 = m0 - b * HW;
    const float* img = g_h2 + (size_t)b * HW * 128;

    int mbase = (w & 3) * 16;
    int nbase = (w >> 2) * 16;
    int qr = l >> 2;
    int qc = l & 3;
    int c0 = 4 * l;

    float4 m4 = *(const float4*)&g_mr[b * 128 + c0];
    float4 r4 = *(const float4*)&g_mr[512 + b * 128 + c0];

    float d[2][4];
#pragma unroll
    for (int j = 0; j < 2; j++)
#pragma unroll
        for (int q = 0; q < 4; q++) d[j][q] = 0.f;

    for (int tap = 0; tap < 9; tap++) {
        __syncthreads();

        // ---- regular tap gather (norm on the fly, zero OOB): 8 px/warp ----
        {
            int dy = tap / 3 - 1, dx = tap % 3 - 1;
#pragma unroll 2
            for (int ii = 0; ii < 8; ii++) {
                int px = w * 8 + ii;
                int s  = s0 + px;
                int y  = s / Wc, xw = s - y * Wc;
                int yy = y + dy, xx = xw + dx;
                float4 v = make_float4(0.f, 0.f, 0.f, 0.f);
                if ((unsigned)yy < Hc && (unsigned)xx < Wc) {
                    float4 raw = *(const float4*)&img[(size_t)(yy * Wc + xx) * 128 + c0];
                    v.x = (raw.x - m4.x) * r4.x;
                    v.y = (raw.y - m4.y) * r4.y;
                    v.z = (raw.z - m4.z) * r4.z;
                    v.w = (raw.w - m4.w) * r4.w;
                }
                *(float4*)&As[px * PITCH + c0] = v;
            }
        }

        // ---- copy B tap [32 x 128] ----
        {
            const float4* src = (const float4*)(g_offwB + (tap << 12));
#pragma unroll
            for (int j = 0; j < 4; j++) {
                int f4 = t + j * 256;
                int n = f4 >> 5, c4 = (f4 & 31) << 2;
                *(float4*)&Bs[n * PITCH + c4] = src[f4];
            }
        }
        __syncthreads();

        // ---- 16 K8-steps, TF32x2 (AhBh + AlBh) ----
#pragma unroll 4
        for (int s = 0; s < 16; s++) {
            int k0 = s * 8;
            uint32_t ah[4], al[4];
            {
                int r0 = (mbase + qr) * PITCH + k0 + qc;
                int r1 = r0 + 8 * PITCH;
                float f0 = As[r0], f1 = As[r1], f2 = As[r0 + 4], f3 = As[r1 + 4];
                ah[0] = tf32r(f0); ah[1] = tf32r(f1);
                ah[2] = tf32r(f2); ah[3] = tf32r(f3);
                al[0] = __float_as_uint(f0 - __uint_as_float(ah[0]));
                al[1] = __float_as_uint(f1 - __uint_as_float(ah[1]));
                al[2] = __float_as_uint(f2 - __uint_as_float(ah[2]));
                al[3] = __float_as_uint(f3 - __uint_as_float(ah[3]));
            }
            uint32_t bh[2][2];
#pragma unroll
            for (int ni = 0; ni < 2; ni++) {
                if (nbase + ni * 8 < 24) {
                    int nb = (nbase + ni * 8 + qr) * PITCH + k0 + qc;
                    bh[ni][0] = tf32r(Bs[nb]);
                    bh[ni][1] = tf32r(Bs[nb + 4]);
                }
            }
#pragma unroll
            for (int ni = 0; ni < 2; ni++)
                if (nbase + ni * 8 < 24) {
                    MMA_TF32(d[ni], ah, bh[ni][0], bh[ni][1]);
                    MMA_TF32(d[ni], al, bh[ni][0], bh[ni][1]);
                }
        }
    }

    // ---- epilogue: bias + write n<18 directly to g_off ----
    {
        int row = mbase + qr;
#pragma unroll
        for (int ni = 0; ni < 2; ni++) {
            int col = nbase + ni * 8 + 2 * qc;
            if (col < 18) {
                float b0 = off_b[col], b1 = off_b[col + 1];
                float2 lo, hi;
                lo.x = d[ni][0] + b0; lo.y = d[ni][1] + b1;
                hi.x = d[ni][2] + b0; hi.y = d[ni][3] + b1;
                *(float2*)&g_off[(size_t)(m0 + row) * 18 + col]     = lo;
                *(float2*)&g_off[(size_t)(m0 + row + 8) * 18 + col] = hi;
            }
        }
    }
}

// ---------------------------------------------------------------------------
// Fused deform conv via mma.sync m16n8k8 TF32x3, norm folded into gather.
// Block: 128 px (M) x 128 out (N), 256 threads = 8 warps (2M x 4N).
// B is K-chunked (2 x 64 cols) so smem = 100KB -> 2 CTAs/SM; halves B traffic.
// ---------------------------------------------------------------------------
#define FUSED_SMEM ((128 * PITCH + 128 * BPITCH) * 4)

__global__ __launch_bounds__(256, 2) void fused_kernel(
        const float* __restrict__ dc_b,
        const float* __restrict__ ln_g,
        const float* __restrict__ ln_b,
        float* __restrict__ out) {
    extern __shared__ float smf[];
    float* As = smf;                      // [px][PITCH], 128 rows
    float* Bs = smf + 128 * PITCH;        // [n][BPITCH], 128 rows (64-col chunk)

    int t = threadIdx.x;
    int w = t >> 5, l = t & 31;
    int m0 = blockIdx.x * 128;
    int b  = m0 / HW;
    int s0 = m0 - b * HW;
    const float* img = g_h2 + (size_t)b * HW * 128;

    int mbase = (w & 1) * 64;             // 4 m-tiles per warp
    int nbase = (w >> 1) * 32;            // 4 n-tiles per warp
    int qr = l >> 2;
    int qc = l & 3;
    int c0 = 4 * l;

    float4 m4 = *(const float4*)&g_mr[b * 128 + c0];
    float4 r4 = *(const float4*)&g_mr[512 + b * 128 + c0];

    float d[4][4][4];
#pragma unroll
    for (int i = 0; i < 4; i++)
#pragma unroll
        for (int j = 0; j < 4; j++)
#pragma unroll
            for (int q = 0; q < 4; q++) d[i][j][q] = 0.f;

    for (int tap = 0; tap < 9; tap++) {
        __syncthreads();   // prev tap fully consumed (As + Bs free)

        // ---- bilinear gather tap into As: 16 px/warp ----
        {
            int dy = tap / 3 - 1, dx = tap % 3 - 1;
#pragma unroll 2
            for (int ii = 0; ii < 16; ii++) {
                int px = w * 16 + ii;
                int s  = s0 + px;
                int y  = s / Wc, xw = s - y * Wc;
                float2 o = *(const float2*)&g_off[(size_t)(m0 + px) * 18 + 2 * tap];
                float ys = (float)(y + dy) + o.x;
                float xs = (float)(xw + dx) + o.y;
                float y0f = floorf(ys), x0f = floorf(xs);
                float wy = ys - y0f, wx = xs - x0f;
                int y0i = (int)y0f, x0i = (int)x0f;
                int y1i = y0i + 1, x1i = x0i + 1;
                float w00 = (1.f - wy) * (1.f - wx);
                float w01 = (1.f - wy) * wx;
                float w10 = wy * (1.f - wx);
                float w11 = wy * wx;
                bool vy0 = (unsigned)y0i < (unsigned)Hc;
                bool vy1 = (unsigned)y1i < (unsigned)Hc;
                bool vx0 = (unsigned)x0i < (unsigned)Wc;
                bool vx1 = (unsigned)x1i < (unsigned)Wc;
                if (!(vy0 && vx0)) w00 = 0.f;
                if (!(vy0 && vx1)) w01 = 0.f;
                if (!(vy1 && vx0)) w10 = 0.f;
                if (!(vy1 && vx1)) w11 = 0.f;
                float wsum = w00 + w01 + w10 + w11;
                int yc0 = min(Hc - 1, max(0, y0i));
                int yc1 = min(Hc - 1, max(0, y1i));
                int xc0 = min(Wc - 1, max(0, x0i));
                int xc1 = min(Wc - 1, max(0, x1i));
                float4 v00 = *(const float4*)&img[(size_t)(yc0 * Wc + xc0) * 128 + c0];
                float4 v01 = *(const float4*)&img[(size_t)(yc0 * Wc + xc1) * 128 + c0];
                float4 v10 = *(const float4*)&img[(size_t)(yc1 * Wc + xc0) * 128 + c0];
                float4 v11 = *(const float4*)&img[(size_t)(yc1 * Wc + xc1) * 128 + c0];
                float4 r;
                r.x = w00 * v00.x + w01 * v01.x + w10 * v10.x + w11 * v11.x;
                r.y = w00 * v00.y + w01 * v01.y + w10 * v10.y + w11 * v11.y;
                r.z = w00 * v00.z + w01 * v01.z + w10 * v10.z + w11 * v11.z;
                r.w = w00 * v00.w + w01 * v01.w + w10 * v10.w + w11 * v11.w;
                r.x = (r.x - m4.x * wsum) * r4.x;
                r.y = (r.y - m4.y * wsum) * r4.y;
                r.z = (r.z - m4.z * wsum) * r4.z;
                r.w = (r.w - m4.w * wsum) * r4.w;
                *(float4*)&As[px * PITCH + c0] = r;
            }
        }

        // ---- two 64-col B chunks per tap ----
#pragma unroll 1
        for (int kb = 0; kb < 2; kb++) {
            if (kb) __syncthreads();   // chunk-0 MMAs done before Bs rewrite
            {
                const float* src = g_wB + (tap << 14) + kb * 64;
#pragma unroll
                for (int j = 0; j < 8; j++) {
                    int f4 = t + j * 256;          // 0..2047
                    int n  = f4 >> 4;              // 16 float4 per 64-col row
                    int c4 = (f4 & 15) << 2;
                    *(float4*)&Bs[n * BPITCH + c4] =
                        *(const float4*)&src[n * 128 + c4];
                }
            }
            __syncthreads();           // Bs (and As for kb=0) visible

            // ---- 8 K8-steps of TF32x3 mma ----
#pragma unroll 2
            for (int s = 0; s < 8; s++) {
                int kA = kb * 64 + s * 8 + qc;
                int kB = s * 8 + qc;
                uint32_t bh[4][2], bl[4][2];
#pragma unroll
                for (int ni = 0; ni < 4; ni++) {
                    int nb = (nbase + ni * 8 + qr) * BPITCH + kB;
                    float f0 = Bs[nb], f1 = Bs[nb + 4];
                    bh[ni][0] = tf32r(f0);
                    bh[ni][1] = tf32r(f1);
                    bl[ni][0] = __float_as_uint(f0 - __uint_as_float(bh[ni][0]));
                    bl[ni][1] = __float_as_uint(f1 - __uint_as_float(bh[ni][1]));
                }
#pragma unroll
                for (int mi = 0; mi < 4; mi++) {
                    uint32_t ah[4], al[4];
                    int r0 = (mbase + mi * 16 + qr) * PITCH + kA;
                    int r1 = r0 + 8 * PITCH;
                    float f0 = As[r0], f1 = As[r1], f2 = As[r0 + 4], f3 = As[r1 + 4];
                    ah[0] = tf32r(f0); ah[1] = tf32r(f1);
                    ah[2] = tf32r(f2); ah[3] = tf32r(f3);
                    al[0] = __float_as_uint(f0 - __uint_as_float(ah[0]));
                    al[1] = __float_as_uint(f1 - __uint_as_float(ah[1]));
                    al[2] = __float_as_uint(f2 - __uint_as_float(ah[2]));
                    al[3] = __float_as_uint(f3 - __uint_as_float(ah[3]));
#pragma unroll
                    for (int ni = 0; ni < 4; ni++) {
                        MMA_TF32(d[mi][ni], ah, bh[ni][0], bh[ni][1]);
                        MMA_TF32(d[mi][ni], ah, bl[ni][0], bl[ni][1]);
                        MMA_TF32(d[mi][ni], al, bh[ni][0], bh[ni][1]);
                    }
                }
            }
        }
    }

    // ---- epilogue: bias + stage into sdc[px][PITCH] ----
    __syncthreads();
    float* sdc = smf;
#pragma unroll
    for (int mi = 0; mi < 4; mi++) {
        int row0 = mbase + mi * 16 + qr;
#pragma unroll
        for (int ni = 0; ni < 4; ni++) {
            int col = nbase + ni * 8 + 2 * qc;
            float b0 = dc_b[col], b1 = dc_b[col + 1];
            float2 lo, hi;
            lo.x = d[mi][ni][0] + b0; lo.y = d[mi][ni][1] + b1;
            hi.x = d[mi][ni][2] + b0; hi.y = d[mi][ni][3] + b1;
            *(float2*)&sdc[row0 * PITCH + col]       = lo;
            *(float2*)&sdc[(row0 + 8) * PITCH + col] = hi;
        }
    }
    __syncthreads();

    // ---- LayerNorm(C) + sigmoid gate (gate reads g_h2 + on-the-fly norm) ----
    {
        float4 gv = *(const float4*)&ln_g[c0];
        float4 bv = *(const float4*)&ln_b[c0];
#pragma unroll 1
        for (int ii = 0; ii < 16; ii++) {
            int px = w * 16 + ii;
            int pg = m0 + px;
            float4 dd = *(const float4*)&sdc[px * PITCH + c0];
            float s  = dd.x + dd.y + dd.z + dd.w;
            float s2 = dd.x * dd.x + dd.y * dd.y + dd.z * dd.z + dd.w * dd.w;
#pragma unroll
            for (int o = 16; o; o >>= 1) {
                s  += __shfl_xor_sync(0xffffffffu, s,  o);
                s2 += __shfl_xor_sync(0xffffffffu, s2, o);
            }
            float mean = s * (1.f / 128.f);
            float var  = s2 * (1.f / 128.f) - mean * mean;
            float rstd = rsqrtf(var + 1e-5f);
            float4 raw = *(const float4*)&g_h2[(size_t)pg * 128 + c0];
            float4 ds;
            ds.x = (raw.x - m4.x) * r4.x;
            ds.y = (raw.y - m4.y) * r4.y;
            ds.z = (raw.z - m4.z) * r4.z;
            ds.w = (raw.w - m4.w) * r4.w;
            float a;
            float4 r;
            a = (dd.x - mean) * rstd * gv.x + bv.x; r.x = ds.x / (1.f + expf(-a));
            a = (dd.y - mean) * rstd * gv.y + bv.y; r.y = ds.y / (1.f + expf(-a));
            a = (dd.z - mean) * rstd * gv.z + bv.z; r.z = ds.z / (1.f + expf(-a));
            a = (dd.w - mean) * rstd * gv.w + bv.w; r.w = ds.w / (1.f + expf(-a));
            *(float4*)&sdc[px * PITCH + c0] = r;
        }
    }
    __syncthreads();

    // ---- transpose-out: sdc[px][c] -> NCHW, coalesced ----
    {
        float* obase = out + (size_t)b * 128 * HW + s0;
#pragma unroll 1
        for (int j = 0; j < 64; j++) {
            int flat = t + j * 256;            // 0..16383
            int c = flat >> 7, px = flat & 127;
            obase[(size_t)c * HW + px] = sdc[px * PITCH + c];
        }
    }
}

// ---------------------------------------------------------------------------
extern "C" void kernel_launch(void* const* d_in, const int* in_sizes, int n_in,
                              void* d_out, int out_size) {
    const float* x     = (const float*)d_in[0];
    const float* dw_w  = (const float*)d_in[1];
    const float* dw_b  = (const float*)d_in[2];
    const float* pw_w  = (const float*)d_in[3];
    const float* pw_b  = (const float*)d_in[4];
    const float* off_w = (const float*)d_in[5];
    const float* off_b = (const float*)d_in[6];
    const float* dc_w  = (const float*)d_in[7];
    const float* dc_b  = (const float*)d_in[8];
    const float* ln_g  = (const float*)d_in[9];
    const float* ln_b  = (const float*)d_in[10];
    float* out = (float*)d_out;

    cudaFuncSetAttribute(dwpw_kernel, cudaFuncAttributeMaxDynamicSharedMemorySize,
                         DWPW_SMEM);
    cudaFuncSetAttribute(off_mma_kernel, cudaFuncAttributeMaxDynamicSharedMemorySize,
                         OFF_SMEM);
    cudaFuncSetAttribute(fused_kernel, cudaFuncAttributeMaxDynamicSharedMemorySize,
                         FUSED_SMEM);

    prep_kernel<<<576, 256>>>(dc_w, off_w);
    dwpw_kernel<<<1152, 256, DWPW_SMEM>>>(x, dw_w, dw_b, pw_w, pw_b);
    mr_kernel<<<2, 256>>>();
    off_mma_kernel<<<576, 256, OFF_SMEM>>>(off_b);
    fused_kernel<<<288, 256, FUSED_SMEM>>>(dc_b, ln_g, ln_b, out);
}

// round 17
// speedup vs baseline: 1.2293x; 1.2293x over previous
#include <cuda_runtime.h>
#include <cstdint>

// ---------------------------------------------------------------------------
// DASAttentionGate. B=4, C=O=128, H=W=96, fp32.
// [dw3x3 + pw1x1(TF32x3 MMA) + stats] -> mr -> offconv3x3 (TF32x2, M=128)
//   -> [fused M=128: gather(norm on the fly) -> TF32x2 MMA -> LN -> gate]
// ---------------------------------------------------------------------------

#define Cc   128
#define Hc   96
#define Wc   96
#define HW   9216
#define PIX  36864
#define PITCH 132
#define BPITCH 68

__device__ float g_h2[PIX * Cc];          // pw out, NHWC (pre-norm)
__device__ float g_stats[1024];
__device__ float g_mr[1024];              // mean[512], rstd[512]
__device__ float g_off[PIX * 18];
__device__ float g_offwB[9 * 32 * 128];   // off weights per tap [n(pad32)][c]
__device__ float g_wB[9 * 16384];         // deform weights per tap: [n*128+c]

// -------------------- TF32 helpers ------------------------------------------
__device__ __forceinline__ uint32_t tf32r(float v) {
    uint32_t r;
    asm("cvt.rna.tf32.f32 %0, %1;" : "=r"(r) : "f"(v));
    return r;
}

#define MMA_TF32(D, A, B0, B1)                                              \
    asm volatile("mma.sync.aligned.m16n8k8.row.col.f32.tf32.tf32.f32 "      \
        "{%0,%1,%2,%3}, {%4,%5,%6,%7}, {%8,%9}, {%0,%1,%2,%3};"             \
        : "+f"((D)[0]), "+f"((D)[1]), "+f"((D)[2]), "+f"((D)[3])            \
        : "r"((A)[0]), "r"((A)[1]), "r"((A)[2]), "r"((A)[3]),               \
          "r"(B0), "r"(B1))

// -------------------- prep: weight images + zero stats ----------------------
__global__ void prep_kernel(const float* __restrict__ dc_w,
                            const float* __restrict__ off_w) {
    int i = blockIdx.x * blockDim.x + threadIdx.x;
    if (i < 9 * 16384) {
        int tap = i >> 14;
        int r   = i & 16383;
        int n   = r >> 7, c = r & 127;
        g_wB[i] = dc_w[(n * 128 + c) * 9 + tap];
    }
    if (i < 9 * 32 * 128) {
        int tap = i >> 12;
        int r   = i & 4095;
        int n   = r >> 7, c = r & 127;
        g_offwB[i] = (n < 18) ? off_w[(n * 128 + c) * 9 + tap] : 0.f;
    }
    if (i < 1024) g_stats[i] = 0.f;
}

// ---------------------------------------------------------------------------
// Fused depthwise 3x3 + pointwise 1x1 (TF32x3 MMA) + InstanceNorm stats.
// Block = 32 px of one row, 256 threads = 8 warps (2M x 4N), warp M16 x N32.
// ---------------------------------------------------------------------------
#define DWPW_SMEM ((32 * PITCH + 128 * PITCH) * 4)

__global__ __launch_bounds__(256, 2) void dwpw_kernel(
        const float* __restrict__ x,
        const float* __restrict__ dw_w,
        const float* __restrict__ dw_b,
        const float* __restrict__ pw_w,
        const float* __restrict__ pw_b) {
    extern __shared__ float smd[];
    float* As = smd;                    // [px][PITCH], 32 rows
    float* Bs = smd + 32 * PITCH;       // [o][PITCH], 128 rows
    float* xt = Bs;                     // halo aliases Bs: [c][r][34] = 13056

    int t  = threadIdx.x;
    int w  = t >> 5, l = t & 31;
    int p0 = blockIdx.x * 32;
    int b  = p0 / HW;
    int s0 = p0 - b * HW;
    int y  = s0 / Wc;
    int x0 = s0 - y * Wc;

    // ---- halo load ----
    for (int f = t; f < 13056; f += 256) {
        int c   = f / 102;
        int rem = f - c * 102;
        int r   = rem / 34;
        int col = rem - r * 34;
        int yy = y + r - 1, xx = x0 + col - 1;
        float v = 0.f;
        if ((unsigned)yy < Hc && (unsigned)xx < Wc)
            v = x[(size_t)(b * 128 + c) * HW + yy * Wc + xx];
        xt[f] = v;
    }
    __syncthreads();

    // ---- depthwise into As[px][c] ----
    {
        int c   = t >> 1;
        int pxb = (t & 1) * 16;
        float wv[9];
#pragma unroll
        for (int j = 0; j < 9; j++) wv[j] = dw_w[c * 9 + j];
        float bias = dw_b[c];
        float accd[16];
#pragma unroll
        for (int p = 0; p < 16; p++) accd[p] = bias;
#pragma unroll
        for (int r = 0; r < 3; r++)
#pragma unroll
            for (int cc = 0; cc < 3; cc++) {
                float wgt = wv[r * 3 + cc];
                const float* src = &xt[c * 102 + r * 34 + pxb + cc];
#pragma unroll
                for (int p = 0; p < 16; p++) accd[p] += wgt * src[p];
            }
#pragma unroll
        for (int p = 0; p < 16; p++) As[(pxb + p) * PITCH + c] = accd[p];
    }
    __syncthreads();

    // ---- load pw weights into Bs[o][c] (overwrites halo) ----
#pragma unroll
    for (int j = 0; j < 16; j++) {
        int f4 = t + j * 256;
        int n = f4 >> 5, c4 = (f4 & 31) << 2;
        *(float4*)&Bs[n * PITCH + c4] = *(const float4*)&pw_w[n * 128 + c4];
    }
    __syncthreads();

    // ---- pw GEMM: [32 x 128] * [128 x 128], TF32x3 ----
    int mbase = (w & 1) * 16;
    int nbase = (w >> 1) * 32;
    int qr = l >> 2;
    int qc = l & 3;

    float d[4][4];
#pragma unroll
    for (int j = 0; j < 4; j++)
#pragma unroll
        for (int q = 0; q < 4; q++) d[j][q] = 0.f;

#pragma unroll 4
    for (int s = 0; s < 16; s++) {
        int k0 = s * 8;
        uint32_t ah[4], al[4];
        {
            int r0 = (mbase + qr) * PITCH + k0 + qc;
            int r1 = r0 + 8 * PITCH;
            float f0 = As[r0], f1 = As[r1], f2 = As[r0 + 4], f3 = As[r1 + 4];
            ah[0] = tf32r(f0); ah[1] = tf32r(f1);
            ah[2] = tf32r(f2); ah[3] = tf32r(f3);
            al[0] = __float_as_uint(f0 - __uint_as_float(ah[0]));
            al[1] = __float_as_uint(f1 - __uint_as_float(ah[1]));
            al[2] = __float_as_uint(f2 - __uint_as_float(ah[2]));
            al[3] = __float_as_uint(f3 - __uint_as_float(ah[3]));
        }
        uint32_t bh[4][2], bl[4][2];
#pragma unroll
        for (int ni = 0; ni < 4; ni++) {
            int nb = (nbase + ni * 8 + qr) * PITCH + k0 + qc;
            float f0 = Bs[nb], f1 = Bs[nb + 4];
            bh[ni][0] = tf32r(f0);
            bh[ni][1] = tf32r(f1);
            bl[ni][0] = __float_as_uint(f0 - __uint_as_float(bh[ni][0]));
            bl[ni][1] = __float_as_uint(f1 - __uint_as_float(bh[ni][1]));
        }
#pragma unroll
        for (int ni = 0; ni < 4; ni++) {
            MMA_TF32(d[ni], ah, bh[ni][0], bh[ni][1]);
            MMA_TF32(d[ni], ah, bl[ni][0], bl[ni][1]);
            MMA_TF32(d[ni], al, bh[ni][0], bh[ni][1]);
        }
    }
    __syncthreads();

    // ---- bias + stage result back into As (sdc[32][PITCH]) ----
    float* sdc = As;
    {
        int row = mbase + qr;
#pragma unroll
        for (int ni = 0; ni < 4; ni++) {
            int col = nbase + ni * 8 + 2 * qc;
            float b0 = pw_b[col], b1 = pw_b[col + 1];
            float2 lo, hi;
            lo.x = d[ni][0] + b0; lo.y = d[ni][1] + b1;
            hi.x = d[ni][2] + b0; hi.y = d[ni][3] + b1;
            *(float2*)&sdc[row * PITCH + col]       = lo;
            *(float2*)&sdc[(row + 8) * PITCH + col] = hi;
        }
    }
    __syncthreads();

    // ---- stats + write g_h2 ----
    {
        int c   = t >> 1;
        int pxb = (t & 1) * 16;
        float sp = 0.f, sq = 0.f;
#pragma unroll
        for (int p = 0; p < 16; p++) {
            float v = sdc[(pxb + p) * PITCH + c];
            sp += v; sq += v * v;
        }
        sp += __shfl_xor_sync(0xffffffffu, sp, 1);
        sq += __shfl_xor_sync(0xffffffffu, sq, 1);
        if ((t & 1) == 0) {
            atomicAdd(&g_stats[b * 128 + c], sp);
            atomicAdd(&g_stats[512 + b * 128 + c], sq);
        }
    }
#pragma unroll
    for (int j = 0; j < 16; j++) {
        int flat = t + j * 256;
        int px = flat >> 7, c = flat & 127;
        g_h2[(size_t)(p0 + px) * 128 + c] = sdc[px * PITCH + c];
    }
}

// -------------------- instance norm finalize ---------------------------------
__global__ void mr_kernel() {
    int i = blockIdx.x * blockDim.x + threadIdx.x;
    if (i >= 512) return;
    float m = g_stats[i] * (1.f / HW);
    float v = g_stats[512 + i] * (1.f / HW) - m * m;
    g_mr[i] = m;
    g_mr[512 + i] = rsqrtf(v + 1e-5f);
}

// ---------------------------------------------------------------------------
// Offset conv 3x3 via TF32x2 MMA: [128px x 1152] * [1152 x 18(pad32)].
// Block: 128 px, 256 threads = 8 warps (4M x 2N), warp M32 x N16. Grid 288.
// ---------------------------------------------------------------------------
#define OFF_SMEM ((128 * PITCH + 32 * PITCH) * 4)

__global__ __launch_bounds__(256, 2) void off_mma_kernel(
        const float* __restrict__ off_b) {
    extern __shared__ float smo[];
    float* As = smo;                    // [px][PITCH], 128 rows
    float* Bs = smo + 128 * PITCH;      // [n][PITCH], 32 rows

    int t = threadIdx.x;
    int w = t >> 5, l = t & 31;
    int m0 = blockIdx.x * 128;
    int b  = m0 / HW;
    int s0 = m0 - b * HW;
    const float* img = g_h2 + (size_t)b * HW * 128;

    int mbase = (w & 3) * 32;
    int nbase = (w >> 2) * 16;
    int qr = l >> 2;
    int qc = l & 3;
    int c0 = 4 * l;

    float4 m4 = *(const float4*)&g_mr[b * 128 + c0];
    float4 r4 = *(const float4*)&g_mr[512 + b * 128 + c0];

    float d[2][2][4];
#pragma unroll
    for (int i = 0; i < 2; i++)
#pragma unroll
        for (int j = 0; j < 2; j++)
#pragma unroll
            for (int q = 0; q < 4; q++) d[i][j][q] = 0.f;

    for (int tap = 0; tap < 9; tap++) {
        __syncthreads();

        // ---- regular tap gather (norm on the fly, zero OOB): 16 px/warp ----
        {
            int dy = tap / 3 - 1, dx = tap % 3 - 1;
#pragma unroll 2
            for (int ii = 0; ii < 16; ii++) {
                int px = w * 16 + ii;
                int s  = s0 + px;
                int y  = s / Wc, xw = s - y * Wc;
                int yy = y + dy, xx = xw + dx;
                float4 v = make_float4(0.f, 0.f, 0.f, 0.f);
                if ((unsigned)yy < Hc && (unsigned)xx < Wc) {
                    float4 raw = *(const float4*)&img[(size_t)(yy * Wc + xx) * 128 + c0];
                    v.x = (raw.x - m4.x) * r4.x;
                    v.y = (raw.y - m4.y) * r4.y;
                    v.z = (raw.z - m4.z) * r4.z;
                    v.w = (raw.w - m4.w) * r4.w;
                }
                *(float4*)&As[px * PITCH + c0] = v;
            }
        }

        // ---- copy B tap [32 x 128] ----
        {
            const float4* src = (const float4*)(g_offwB + (tap << 12));
#pragma unroll
            for (int j = 0; j < 4; j++) {
                int f4 = t + j * 256;
                int n = f4 >> 5, c4 = (f4 & 31) << 2;
                *(float4*)&Bs[n * PITCH + c4] = src[f4];
            }
        }
        __syncthreads();

        // ---- 16 K8-steps, TF32x2 (AhBh + AlBh) ----
#pragma unroll 4
        for (int s = 0; s < 16; s++) {
            int k0 = s * 8;
            uint32_t ah[2][4], al[2][4];
#pragma unroll
            for (int mi = 0; mi < 2; mi++) {
                int r0 = (mbase + mi * 16 + qr) * PITCH + k0 + qc;
                int r1 = r0 + 8 * PITCH;
                float f0 = As[r0], f1 = As[r1], f2 = As[r0 + 4], f3 = As[r1 + 4];
                ah[mi][0] = tf32r(f0); ah[mi][1] = tf32r(f1);
                ah[mi][2] = tf32r(f2); ah[mi][3] = tf32r(f3);
                al[mi][0] = __float_as_uint(f0 - __uint_as_float(ah[mi][0]));
                al[mi][1] = __float_as_uint(f1 - __uint_as_float(ah[mi][1]));
                al[mi][2] = __float_as_uint(f2 - __uint_as_float(ah[mi][2]));
                al[mi][3] = __float_as_uint(f3 - __uint_as_float(ah[mi][3]));
            }
            uint32_t bh[2][2];
#pragma unroll
            for (int ni = 0; ni < 2; ni++) {
                if (nbase + ni * 8 < 24) {
                    int nb = (nbase + ni * 8 + qr) * PITCH + k0 + qc;
                    bh[ni][0] = tf32r(Bs[nb]);
                    bh[ni][1] = tf32r(Bs[nb + 4]);
                }
            }
#pragma unroll
            for (int mi = 0; mi < 2; mi++)
#pragma unroll
                for (int ni = 0; ni < 2; ni++)
                    if (nbase + ni * 8 < 24) {
                        MMA_TF32(d[mi][ni], ah[mi], bh[ni][0], bh[ni][1]);
                        MMA_TF32(d[mi][ni], al[mi], bh[ni][0], bh[ni][1]);
                    }
        }
    }

    // ---- epilogue: bias + write n<18 directly to g_off ----
#pragma unroll
    for (int mi = 0; mi < 2; mi++) {
        int row = mbase + mi * 16 + qr;
#pragma unroll
        for (int ni = 0; ni < 2; ni++) {
            int col = nbase + ni * 8 + 2 * qc;
            if (col < 18) {
                float b0 = off_b[col], b1 = off_b[col + 1];
                float2 lo, hi;
                lo.x = d[mi][ni][0] + b0; lo.y = d[mi][ni][1] + b1;
                hi.x = d[mi][ni][2] + b0; hi.y = d[mi][ni][3] + b1;
                *(float2*)&g_off[(size_t)(m0 + row) * 18 + col]     = lo;
                *(float2*)&g_off[(size_t)(m0 + row + 8) * 18 + col] = hi;
            }
        }
    }
}

// ---------------------------------------------------------------------------
// Fused deform conv via mma.sync m16n8k8 TF32x2 (AhBh + AhBl; A-lo dropped).
// Block: 128 px (M) x 128 out (N), 256 threads = 8 warps (2M x 4N).
// B is K-chunked (2 x 64 cols): smem 100KB -> 2 CTAs/SM.
// ---------------------------------------------------------------------------
#define FUSED_SMEM ((128 * PITCH + 128 * BPITCH) * 4)

__global__ __launch_bounds__(256, 2) void fused_kernel(
        const float* __restrict__ dc_b,
        const float* __restrict__ ln_g,
        const float* __restrict__ ln_b,
        float* __restrict__ out) {
    extern __shared__ float smf[];
    float* As = smf;                      // [px][PITCH], 128 rows
    float* Bs = smf + 128 * PITCH;        // [n][BPITCH], 128 rows (64-col chunk)

    int t = threadIdx.x;
    int w = t >> 5, l = t & 31;
    int m0 = blockIdx.x * 128;
    int b  = m0 / HW;
    int s0 = m0 - b * HW;
    const float* img = g_h2 + (size_t)b * HW * 128;

    int mbase = (w & 1) * 64;             // 4 m-tiles per warp
    int nbase = (w >> 1) * 32;            // 4 n-tiles per warp
    int qr = l >> 2;
    int qc = l & 3;
    int c0 = 4 * l;

    float4 m4 = *(const float4*)&g_mr[b * 128 + c0];
    float4 r4 = *(const float4*)&g_mr[512 + b * 128 + c0];

    float d[4][4][4];
#pragma unroll
    for (int i = 0; i < 4; i++)
#pragma unroll
        for (int j = 0; j < 4; j++)
#pragma unroll
            for (int q = 0; q < 4; q++) d[i][j][q] = 0.f;

    for (int tap = 0; tap < 9; tap++) {
        __syncthreads();   // prev tap fully consumed (As + Bs free)

        // ---- bilinear gather tap into As: 16 px/warp ----
        {
            int dy = tap / 3 - 1, dx = tap % 3 - 1;
#pragma unroll 2
            for (int ii = 0; ii < 16; ii++) {
                int px = w * 16 + ii;
                int s  = s0 + px;
                int y  = s / Wc, xw = s - y * Wc;
                float2 o = *(const float2*)&g_off[(size_t)(m0 + px) * 18 + 2 * tap];
                float ys = (float)(y + dy) + o.x;
                float xs = (float)(xw + dx) + o.y;
                float y0f = floorf(ys), x0f = floorf(xs);
                float wy = ys - y0f, wx = xs - x0f;
                int y0i = (int)y0f, x0i = (int)x0f;
                int y1i = y0i + 1, x1i = x0i + 1;
                float w00 = (1.f - wy) * (1.f - wx);
                float w01 = (1.f - wy) * wx;
                float w10 = wy * (1.f - wx);
                float w11 = wy * wx;
                bool vy0 = (unsigned)y0i < (unsigned)Hc;
                bool vy1 = (unsigned)y1i < (unsigned)Hc;
                bool vx0 = (unsigned)x0i < (unsigned)Wc;
                bool vx1 = (unsigned)x1i < (unsigned)Wc;
                if (!(vy0 && vx0)) w00 = 0.f;
                if (!(vy0 && vx1)) w01 = 0.f;
                if (!(vy1 && vx0)) w10 = 0.f;
                if (!(vy1 && vx1)) w11 = 0.f;
                float wsum = w00 + w01 + w10 + w11;
                int yc0 = min(Hc - 1, max(0, y0i));
                int yc1 = min(Hc - 1, max(0, y1i));
                int xc0 = min(Wc - 1, max(0, x0i));
                int xc1 = min(Wc - 1, max(0, x1i));
                float4 v00 = *(const float4*)&img[(size_t)(yc0 * Wc + xc0) * 128 + c0];
                float4 v01 = *(const float4*)&img[(size_t)(yc0 * Wc + xc1) * 128 + c0];
                float4 v10 = *(const float4*)&img[(size_t)(yc1 * Wc + xc0) * 128 + c0];
                float4 v11 = *(const float4*)&img[(size_t)(yc1 * Wc + xc1) * 128 + c0];
                float4 r;
                r.x = w00 * v00.x + w01 * v01.x + w10 * v10.x + w11 * v11.x;
                r.y = w00 * v00.y + w01 * v01.y + w10 * v10.y + w11 * v11.y;
                r.z = w00 * v00.z + w01 * v01.z + w10 * v10.z + w11 * v11.z;
                r.w = w00 * v00.w + w01 * v01.w + w10 * v10.w + w11 * v11.w;
                r.x = (r.x - m4.x * wsum) * r4.x;
                r.y = (r.y - m4.y * wsum) * r4.y;
                r.z = (r.z - m4.z * wsum) * r4.z;
                r.w = (r.w - m4.w * wsum) * r4.w;
                *(float4*)&As[px * PITCH + c0] = r;
            }
        }

        // ---- two 64-col B chunks per tap ----
#pragma unroll 1
        for (int kb = 0; kb < 2; kb++) {
            if (kb) __syncthreads();   // chunk-0 MMAs done before Bs rewrite
            {
                const float* src = g_wB + (tap << 14) + kb * 64;
#pragma unroll
                for (int j = 0; j < 8; j++) {
                    int f4 = t + j * 256;          // 0..2047
                    int n  = f4 >> 4;
                    int c4 = (f4 & 15) << 2;
                    *(float4*)&Bs[n * BPITCH + c4] =
                        *(const float4*)&src[n * 128 + c4];
                }
            }
            __syncthreads();           // Bs (and As for kb=0) visible

            // ---- 8 K8-steps of TF32x2 mma (AhBh + AhBl) ----
#pragma unroll 2
            for (int s = 0; s < 8; s++) {
                int kA = kb * 64 + s * 8 + qc;
                int kB = s * 8 + qc;
                uint32_t bh[4][2], bl[4][2];
#pragma unroll
                for (int ni = 0; ni < 4; ni++) {
                    int nb = (nbase + ni * 8 + qr) * BPITCH + kB;
                    float f0 = Bs[nb], f1 = Bs[nb + 4];
                    bh[ni][0] = tf32r(f0);
                    bh[ni][1] = tf32r(f1);
                    bl[ni][0] = __float_as_uint(f0 - __uint_as_float(bh[ni][0]));
                    bl[ni][1] = __float_as_uint(f1 - __uint_as_float(bh[ni][1]));
                }
#pragma unroll
                for (int mi = 0; mi < 4; mi++) {
                    uint32_t ah[4];
                    int r0 = (mbase + mi * 16 + qr) * PITCH + kA;
                    int r1 = r0 + 8 * PITCH;
                    ah[0] = tf32r(As[r0]);
                    ah[1] = tf32r(As[r1]);
                    ah[2] = tf32r(As[r0 + 4]);
                    ah[3] = tf32r(As[r1 + 4]);
#pragma unroll
                    for (int ni = 0; ni < 4; ni++) {
                        MMA_TF32(d[mi][ni], ah, bh[ni][0], bh[ni][1]);
                        MMA_TF32(d[mi][ni], ah, bl[ni][0], bl[ni][1]);
                    }
                }
            }
        }
    }

    // ---- epilogue: bias + stage into sdc[px][PITCH] ----
    __syncthreads();
    float* sdc = smf;
#pragma unroll
    for (int mi = 0; mi < 4; mi++) {
        int row0 = mbase + mi * 16 + qr;
#pragma unroll
        for (int ni = 0; ni < 4; ni++) {
            int col = nbase + ni * 8 + 2 * qc;
            float b0 = dc_b[col], b1 = dc_b[col + 1];
            float2 lo, hi;
            lo.x = d[mi][ni][0] + b0; lo.y = d[mi][ni][1] + b1;
            hi.x = d[mi][ni][2] + b0; hi.y = d[mi][ni][3] + b1;
            *(float2*)&sdc[row0 * PITCH + col]       = lo;
            *(float2*)&sdc[(row0 + 8) * PITCH + col] = hi;
        }
    }
    __syncthreads();

    // ---- LayerNorm(C) + sigmoid gate (gate reads g_h2 + on-the-fly norm) ----
    {
        float4 gv = *(const float4*)&ln_g[c0];
        float4 bv = *(const float4*)&ln_b[c0];
#pragma unroll 1
        for (int ii = 0; ii < 16; ii++) {
            int px = w * 16 + ii;
            int pg = m0 + px;
            float4 dd = *(const float4*)&sdc[px * PITCH + c0];
            float s  = dd.x + dd.y + dd.z + dd.w;
            float s2 = dd.x * dd.x + dd.y * dd.y + dd.z * dd.z + dd.w * dd.w;
#pragma unroll
            for (int o = 16; o; o >>= 1) {
                s  += __shfl_xor_sync(0xffffffffu, s,  o);
                s2 += __shfl_xor_sync(0xffffffffu, s2, o);
            }
            float mean = s * (1.f / 128.f);
            float var  = s2 * (1.f / 128.f) - mean * mean;
            float rstd = rsqrtf(var + 1e-5f);
            float4 raw = *(const float4*)&g_h2[(size_t)pg * 128 + c0];
            float4 ds;
            ds.x = (raw.x - m4.x) * r4.x;
            ds.y = (raw.y - m4.y) * r4.y;
            ds.z = (raw.z - m4.z) * r4.z;
            ds.w = (raw.w - m4.w) * r4.w;
            float a;
            float4 r;
            a = (dd.x - mean) * rstd * gv.x + bv.x; r.x = ds.x / (1.f + expf(-a));
            a = (dd.y - mean) * rstd * gv.y + bv.y; r.y = ds.y / (1.f + expf(-a));
            a = (dd.z - mean) * rstd * gv.z + bv.z; r.z = ds.z / (1.f + expf(-a));
            a = (dd.w - mean) * rstd * gv.w + bv.w; r.w = ds.w / (1.f + expf(-a));
            *(float4*)&sdc[px * PITCH + c0] = r;
        }
    }
    __syncthreads();

    // ---- transpose-out: sdc[px][c] -> NCHW, coalesced ----
    {
        float* obase = out + (size_t)b * 128 * HW + s0;
#pragma unroll 1
        for (int j = 0; j < 64; j++) {
            int flat = t + j * 256;
            int c = flat >> 7, px = flat & 127;
            obase[(size_t)c * HW + px] = sdc[px * PITCH + c];
        }
    }
}

// ---------------------------------------------------------------------------
extern "C" void kernel_launch(void* const* d_in, const int* in_sizes, int n_in,
                              void* d_out, int out_size) {
    const float* x     = (const float*)d_in[0];
    const float* dw_w  = (const float*)d_in[1];
    const float* dw_b  = (const float*)d_in[2];
    const float* pw_w  = (const float*)d_in[3];
    const float* pw_b  = (const float*)d_in[4];
    const float* off_w = (const float*)d_in[5];
    const float* off_b = (const float*)d_in[6];
    const float* dc_w  = (const float*)d_in[7];
    const float* dc_b  = (const float*)d_in[8];
    const float* ln_g  = (const float*)d_in[9];
    const float* ln_b  = (const float*)d_in[10];
    float* out = (float*)d_out;

    cudaFuncSetAttribute(dwpw_kernel, cudaFuncAttributeMaxDynamicSharedMemorySize,
                         DWPW_SMEM);
    cudaFuncSetAttribute(off_mma_kernel, cudaFuncAttributeMaxDynamicSharedMemorySize,
                         OFF_SMEM);
    cudaFuncSetAttribute(fused_kernel, cudaFuncAttributeMaxDynamicSharedMemorySize,
                         FUSED_SMEM);

    prep_kernel<<<576, 256>>>(dc_w, off_w);
    dwpw_kernel<<<1152, 256, DWPW_SMEM>>>(x, dw_w, dw_b, pw_w, pw_b);
    mr_kernel<<<2, 256>>>();
    off_mma_kernel<<<288, 256, OFF_SMEM>>>(off_b);
    fused_kernel<<<288, 256, FUSED_SMEM>>>(dc_b, ln_g, ln_b, out);
}